// round 2
// baseline (speedup 1.0000x reference)
#include <cuda_runtime.h>
#include <math.h>

#define BQ 4
#define NQ 4096
#define CQ 768
#define HEADS 12
#define PTS 4
#define HDQ 64
#define HID 3072
#define IMG_H 64
#define IMG_W 64
#define C3 (3*CQ)
#define M_ROWS (BQ*NQ)   /* 16384 */

// ---------------- scratch (static device arrays; no allocation) -------------
__device__ float g_h[(size_t)M_ROWS * CQ];        // LN1 out, reused for LN2 out
__device__ float g_qkv[(size_t)M_ROWS * C3];
__device__ float g_off[(size_t)M_ROWS * HEADS * PTS * 2];
__device__ float g_attn[(size_t)M_ROWS * CQ];
__device__ float g_x1[(size_t)M_ROWS * CQ];
__device__ float g_m[(size_t)M_ROWS * HID];

// ---------------- LayerNorm: one block per row, C = 768 ---------------------
__global__ __launch_bounds__(256) void ln_kernel(
    const float* __restrict__ x, const float* __restrict__ gw,
    const float* __restrict__ gb, float* __restrict__ out)
{
    __shared__ float s_sum[8], s_sq[8];
    int row = blockIdx.x;
    const float* xr = x + (size_t)row * CQ;
    float v[3];
    float s = 0.f, sq = 0.f;
#pragma unroll
    for (int i = 0; i < 3; i++) {
        v[i] = xr[threadIdx.x + i * 256];
        s += v[i];
        sq += v[i] * v[i];
    }
#pragma unroll
    for (int o = 16; o > 0; o >>= 1) {
        s  += __shfl_xor_sync(0xffffffffu, s,  o);
        sq += __shfl_xor_sync(0xffffffffu, sq, o);
    }
    int w = threadIdx.x >> 5, l = threadIdx.x & 31;
    if (l == 0) { s_sum[w] = s; s_sq[w] = sq; }
    __syncthreads();
    if (w == 0) {
        s  = (l < 8) ? s_sum[l] : 0.f;
        sq = (l < 8) ? s_sq[l]  : 0.f;
#pragma unroll
        for (int o = 4; o > 0; o >>= 1) {
            s  += __shfl_xor_sync(0xffffffffu, s,  o);
            sq += __shfl_xor_sync(0xffffffffu, sq, o);
        }
        if (l == 0) { s_sum[0] = s; s_sq[0] = sq; }
    }
    __syncthreads();
    float mean = s_sum[0] * (1.f / CQ);
    float var  = s_sq[0] * (1.f / CQ) - mean * mean;
    float rstd = rsqrtf(var + 1e-5f);
#pragma unroll
    for (int i = 0; i < 3; i++) {
        int c = threadIdx.x + i * 256;
        out[(size_t)row * CQ + c] = (v[i] - mean) * rstd * gw[c] + gb[c];
    }
}

// ---------------- fp32 tiled GEMM: C[m,n] = sum_k A[m,k] * W[n,k] + bias ----
// EPI: 0 = bias only, 1 = bias + residual, 2 = bias + exact GELU
// A row-major with stride lda; W row-major [N, K]; C row-major stride ldc.
// Requires M % 128 == 0, K % 16 == 0 (true for all call sites). N guarded.
template <int EPI>
__global__ __launch_bounds__(256) void gemm_kernel(
    const float* __restrict__ A, int lda,
    const float* __restrict__ Wt,
    const float* __restrict__ bias,
    const float* __restrict__ resid, int ldr,
    float* __restrict__ Cout, int ldc,
    int M, int N, int K)
{
    __shared__ float As[16][132];
    __shared__ float Bs[16][68];
    int tid = threadIdx.x;
    int bm = blockIdx.y * 128;
    int bn = blockIdx.x * 64;
    int tx = tid & 15;   // 0..15 -> 4 cols each
    int ty = tid >> 4;   // 0..15 -> 8 rows each
    float acc[8][4];
#pragma unroll
    for (int i = 0; i < 8; i++)
#pragma unroll
        for (int j = 0; j < 4; j++) acc[i][j] = 0.f;

    int ar = tid >> 2;   // 0..63
    int kq = tid & 3;    // float4 index within 16 k's

    for (int k0 = 0; k0 < K; k0 += 16) {
#pragma unroll
        for (int hh = 0; hh < 2; hh++) {
            int m = ar + hh * 64;
            const float4 v = *reinterpret_cast<const float4*>(
                A + (size_t)(bm + m) * lda + k0 + kq * 4);
            As[kq * 4 + 0][m] = v.x;
            As[kq * 4 + 1][m] = v.y;
            As[kq * 4 + 2][m] = v.z;
            As[kq * 4 + 3][m] = v.w;
        }
        {
            int n = bn + ar;
            float4 v = make_float4(0.f, 0.f, 0.f, 0.f);
            if (n < N)
                v = *reinterpret_cast<const float4*>(
                    Wt + (size_t)n * K + k0 + kq * 4);
            Bs[kq * 4 + 0][ar] = v.x;
            Bs[kq * 4 + 1][ar] = v.y;
            Bs[kq * 4 + 2][ar] = v.z;
            Bs[kq * 4 + 3][ar] = v.w;
        }
        __syncthreads();
#pragma unroll
        for (int k = 0; k < 16; k++) {
            float a[8], bb[4];
#pragma unroll
            for (int i = 0; i < 8; i++) a[i] = As[k][ty * 8 + i];
#pragma unroll
            for (int j = 0; j < 4; j++) bb[j] = Bs[k][tx * 4 + j];
#pragma unroll
            for (int i = 0; i < 8; i++)
#pragma unroll
                for (int j = 0; j < 4; j++) acc[i][j] += a[i] * bb[j];
        }
        __syncthreads();
    }

#pragma unroll
    for (int j = 0; j < 4; j++) {
        int n = bn + tx * 4 + j;
        if (n >= N) continue;
        float bv = bias[n];
#pragma unroll
        for (int i = 0; i < 8; i++) {
            int m = bm + ty * 8 + i;
            float v = acc[i][j] + bv;
            if (EPI == 1) v += resid[(size_t)m * ldr + n];
            if (EPI == 2) v = 0.5f * v * (1.f + erff(v * 0.70710678118654752f));
            Cout[(size_t)m * ldc + n] = v;
        }
    }
}

// ---------------- deformable sampling + 4-point attention -------------------
// One warp per (b, head, n). k_img/v_img are strided views of g_qkv:
// k(b,h,d,y,x) = qkv[b, y*W+x, CQ + h*64 + d].
// grid_sample coords collapse to: x = ref_x*W + off_x - 0.5 (exact algebra).
__global__ __launch_bounds__(128) void deform_attn_kernel(
    const float* __restrict__ qkv, const float* __restrict__ off,
    const float* __restrict__ refp, float* __restrict__ out)
{
    int gwarp = (blockIdx.x * blockDim.x + threadIdx.x) >> 5;
    int lane = threadIdx.x & 31;
    int n = gwarp % NQ;
    int bh = gwarp / NQ;
    int h = bh % HEADS;
    int b = bh / HEADS;

    const float* row = qkv + ((size_t)b * NQ + n) * C3;
    float q0 = row[h * HDQ + lane];
    float q1 = row[h * HDQ + 32 + lane];
    const float* op = off + ((size_t)b * NQ + n) * (HEADS * PTS * 2) + h * PTS * 2;
    float rx = refp[((size_t)b * NQ + n) * 2 + 0];
    float ry = refp[((size_t)b * NQ + n) * 2 + 1];

    const float* kbase = qkv + (size_t)b * NQ * C3 + CQ + h * HDQ;

    float sv0[PTS], sv1[PTS], logit[PTS];
#pragma unroll
    for (int p = 0; p < PTS; p++) {
        float x = rx * (float)IMG_W + op[p * 2 + 0] - 0.5f;
        float y = ry * (float)IMG_H + op[p * 2 + 1] - 0.5f;
        float xf = floorf(x), yf = floorf(y);
        float wx = x - xf, wy = y - yf;
        int x0 = (int)xf, y0 = (int)yf;
        float wgt[4];
        wgt[0] = (1.f - wx) * (1.f - wy);
        wgt[1] = wx * (1.f - wy);
        wgt[2] = (1.f - wx) * wy;
        wgt[3] = wx * wy;
        float k0 = 0.f, k1 = 0.f, v0 = 0.f, v1 = 0.f;
#pragma unroll
        for (int c = 0; c < 4; c++) {
            int ix = x0 + (c & 1);
            int iy = y0 + (c >> 1);
            if (ix >= 0 && ix < IMG_W && iy >= 0 && iy < IMG_H) {
                float w = wgt[c];
                const float* kp = kbase + (size_t)(iy * IMG_W + ix) * C3;
                k0 += w * kp[lane];
                k1 += w * kp[32 + lane];
                v0 += w * kp[CQ + lane];
                v1 += w * kp[CQ + 32 + lane];
            }
        }
        sv0[p] = v0;
        sv1[p] = v1;
        float part = q0 * k0 + q1 * k1;
#pragma unroll
        for (int o = 16; o > 0; o >>= 1)
            part += __shfl_xor_sync(0xffffffffu, part, o);
        logit[p] = part * 0.125f;   // HD^-0.5
    }
    // softmax over PTS=4
    float mx = fmaxf(fmaxf(logit[0], logit[1]), fmaxf(logit[2], logit[3]));
    float e[PTS], esum = 0.f;
#pragma unroll
    for (int p = 0; p < PTS; p++) { e[p] = expf(logit[p] - mx); esum += e[p]; }
    float inv = 1.f / esum;
    float o0 = 0.f, o1 = 0.f;
#pragma unroll
    for (int p = 0; p < PTS; p++) {
        float a = e[p] * inv;
        o0 += a * sv0[p];
        o1 += a * sv1[p];
    }
    float* orow = out + ((size_t)b * NQ + n) * CQ + h * HDQ;
    orow[lane] = o0;
    orow[32 + lane] = o1;
}

// ---------------- launch ----------------------------------------------------
extern "C" void kernel_launch(void* const* d_in, const int* in_sizes, int n_in,
                              void* d_out, int out_size)
{
    (void)in_sizes; (void)n_in; (void)out_size;
    const float* x      = (const float*)d_in[0];
    const float* refp   = (const float*)d_in[1];
    const float* n1w    = (const float*)d_in[2];
    const float* n1b    = (const float*)d_in[3];
    const float* qkv_w  = (const float*)d_in[4];
    const float* qkv_b  = (const float*)d_in[5];
    const float* off_w  = (const float*)d_in[6];
    const float* off_b  = (const float*)d_in[7];
    const float* proj_w = (const float*)d_in[8];
    const float* proj_b = (const float*)d_in[9];
    const float* n2w    = (const float*)d_in[10];
    const float* n2b    = (const float*)d_in[11];
    const float* fc1_w  = (const float*)d_in[12];
    const float* fc1_b  = (const float*)d_in[13];
    const float* fc2_w  = (const float*)d_in[14];
    const float* fc2_b  = (const float*)d_in[15];
    float* out = (float*)d_out;

    float *h_p, *qkv_p, *off_p, *attn_p, *x1_p, *m_p;
    cudaGetSymbolAddress((void**)&h_p,    g_h);
    cudaGetSymbolAddress((void**)&qkv_p,  g_qkv);
    cudaGetSymbolAddress((void**)&off_p,  g_off);
    cudaGetSymbolAddress((void**)&attn_p, g_attn);
    cudaGetSymbolAddress((void**)&x1_p,   g_x1);
    cudaGetSymbolAddress((void**)&m_p,    g_m);

    // 1. h = LN1(x)
    ln_kernel<<<M_ROWS, 256>>>(x, n1w, n1b, h_p);
    // 2. qkv = h @ qkv_w.T + qkv_b
    gemm_kernel<0><<<dim3(C3 / 64, M_ROWS / 128), 256>>>(
        h_p, CQ, qkv_w, qkv_b, nullptr, 0, qkv_p, C3, M_ROWS, C3, CQ);
    // 3. offsets = q @ off_w.T + off_b   (q = qkv[:, :768] via lda)
    gemm_kernel<0><<<dim3(2, M_ROWS / 128), 256>>>(
        qkv_p, C3, off_w, off_b, nullptr, 0, off_p, HEADS * PTS * 2,
        M_ROWS, HEADS * PTS * 2, CQ);
    // 4. deformable sampling + attention
    deform_attn_kernel<<<(M_ROWS * HEADS) / 4, 128>>>(qkv_p, off_p, refp, attn_p);
    // 5. x1 = x + attn @ proj_w.T + proj_b
    gemm_kernel<1><<<dim3(CQ / 64, M_ROWS / 128), 256>>>(
        attn_p, CQ, proj_w, proj_b, x, CQ, x1_p, CQ, M_ROWS, CQ, CQ);
    // 6. h2 = LN2(x1)
    ln_kernel<<<M_ROWS, 256>>>(x1_p, n2w, n2b, h_p);
    // 7. m = gelu(h2 @ fc1_w.T + fc1_b)
    gemm_kernel<2><<<dim3(HID / 64, M_ROWS / 128), 256>>>(
        h_p, CQ, fc1_w, fc1_b, nullptr, 0, m_p, HID, M_ROWS, HID, CQ);
    // 8. out = x1 + m @ fc2_w.T + fc2_b
    gemm_kernel<1><<<dim3(CQ / 64, M_ROWS / 128), 256>>>(
        m_p, HID, fc2_w, fc2_b, x1_p, CQ, out, CQ, M_ROWS, CQ, HID);
}

// round 11
// speedup vs baseline: 2.3873x; 2.3873x over previous
#include <cuda_runtime.h>
#include <math.h>
#include <stdint.h>

#define BQ 4
#define NQ 4096
#define CQ 768
#define HEADS 12
#define PTS 4
#define HDQ 64
#define HID 3072
#define IMG_H 64
#define IMG_W 64
#define C3 (3*CQ)
#define M_ROWS (BQ*NQ)   /* 16384 */

// ---------------- scratch (static device arrays; no allocation) -------------
__device__ float g_h[(size_t)M_ROWS * CQ];        // LN1 out, reused for LN2 out
__device__ float g_qkv[(size_t)M_ROWS * C3];
__device__ float g_off[(size_t)M_ROWS * HEADS * PTS * 2];
__device__ float g_attn[(size_t)M_ROWS * CQ];
__device__ float g_x1[(size_t)M_ROWS * CQ];
__device__ float g_m[(size_t)M_ROWS * HID];

// ---------------- LayerNorm: one block per row, C = 768 ---------------------
__global__ __launch_bounds__(256) void ln_kernel(
    const float* __restrict__ x, const float* __restrict__ gw,
    const float* __restrict__ gb, float* __restrict__ out)
{
    __shared__ float s_sum[8], s_sq[8];
    int row = blockIdx.x;
    const float* xr = x + (size_t)row * CQ;
    float v[3];
    float s = 0.f, sq = 0.f;
#pragma unroll
    for (int i = 0; i < 3; i++) {
        v[i] = xr[threadIdx.x + i * 256];
        s += v[i];
        sq += v[i] * v[i];
    }
#pragma unroll
    for (int o = 16; o > 0; o >>= 1) {
        s  += __shfl_xor_sync(0xffffffffu, s,  o);
        sq += __shfl_xor_sync(0xffffffffu, sq, o);
    }
    int w = threadIdx.x >> 5, l = threadIdx.x & 31;
    if (l == 0) { s_sum[w] = s; s_sq[w] = sq; }
    __syncthreads();
    if (w == 0) {
        s  = (l < 8) ? s_sum[l] : 0.f;
        sq = (l < 8) ? s_sq[l]  : 0.f;
#pragma unroll
        for (int o = 4; o > 0; o >>= 1) {
            s  += __shfl_xor_sync(0xffffffffu, s,  o);
            sq += __shfl_xor_sync(0xffffffffu, sq, o);
        }
        if (l == 0) { s_sum[0] = s; s_sq[0] = sq; }
    }
    __syncthreads();
    float mean = s_sum[0] * (1.f / CQ);
    float var  = s_sq[0] * (1.f / CQ) - mean * mean;
    float rstd = rsqrtf(var + 1e-5f);
#pragma unroll
    for (int i = 0; i < 3; i++) {
        int c = threadIdx.x + i * 256;
        out[(size_t)row * CQ + c] = (v[i] - mean) * rstd * gw[c] + gb[c];
    }
}

// ---------------- TF32 tensor-core GEMM -------------------------------------
// C[m,n] = sum_k A[m,k] * W[n,k] + bias[n]   (EPI 0: bias, 1: +resid, 2: GELU)
// mma.sync.m16n8k8.row.col: A row-major, B "col-major" == W[n][k] row-major.
// CTA tile 128x128x16, 8 warps (4m x 2n), warp tile 32x64.
// Smem padded to 20 floats/row: fragment loads conflict-free.
__device__ __forceinline__ uint32_t f2tf32(float f) {
    uint32_t u;
    asm("cvt.rna.tf32.f32 %0, %1;" : "=r"(u) : "f"(f));
    return u;
}

__device__ __forceinline__ void mma_tf32(
    float c[4], const uint32_t a[4], uint32_t b0, uint32_t b1)
{
    asm volatile(
        "mma.sync.aligned.m16n8k8.row.col.f32.tf32.tf32.f32 "
        "{%0,%1,%2,%3}, {%4,%5,%6,%7}, {%8,%9}, {%0,%1,%2,%3};"
        : "+f"(c[0]), "+f"(c[1]), "+f"(c[2]), "+f"(c[3])
        : "r"(a[0]), "r"(a[1]), "r"(a[2]), "r"(a[3]), "r"(b0), "r"(b1));
}

template <int EPI>
__global__ __launch_bounds__(256) void gemm_tf32(
    const float* __restrict__ A, int lda,
    const float* __restrict__ Wt,
    const float* __restrict__ bias,
    const float* __restrict__ resid, int ldr,
    float* __restrict__ Cout, int ldc,
    int M, int N, int K)
{
    __shared__ uint32_t As[2][128][20];
    __shared__ uint32_t Bs[2][128][20];

    int tid  = threadIdx.x;
    int bm   = blockIdx.y * 128;
    int bn   = blockIdx.x * 128;
    int w    = tid >> 5;
    int lane = tid & 31;
    int gid  = lane >> 2;
    int tig  = lane & 3;
    int wm   = (w & 3) * 32;
    int wn   = (w >> 2) * 64;

    int lr   = tid >> 2;     // 0..63 load row
    int lc   = (tid & 3) * 4; // float4 col offset

    float acc[2][8][4];
#pragma unroll
    for (int mt = 0; mt < 2; mt++)
#pragma unroll
        for (int nt = 0; nt < 8; nt++)
#pragma unroll
            for (int i = 0; i < 4; i++) acc[mt][nt][i] = 0.f;

    int niter = K >> 4;
    float4 ar[2], br[2];

    // ---- load tile 0 into regs ----
    {
#pragma unroll
        for (int hh = 0; hh < 2; hh++) {
            ar[hh] = *reinterpret_cast<const float4*>(
                A + (size_t)(bm + lr + hh * 64) * lda + lc);
            int n = bn + lr + hh * 64;
            br[hh] = (n < N)
                ? *reinterpret_cast<const float4*>(Wt + (size_t)n * K + lc)
                : make_float4(0.f, 0.f, 0.f, 0.f);
        }
    }
    // ---- store tile 0 to smem[0] ----
#pragma unroll
    for (int hh = 0; hh < 2; hh++) {
        uint32_t* ap = &As[0][lr + hh * 64][lc];
        ap[0] = f2tf32(ar[hh].x); ap[1] = f2tf32(ar[hh].y);
        ap[2] = f2tf32(ar[hh].z); ap[3] = f2tf32(ar[hh].w);
        uint32_t* bp = &Bs[0][lr + hh * 64][lc];
        bp[0] = f2tf32(br[hh].x); bp[1] = f2tf32(br[hh].y);
        bp[2] = f2tf32(br[hh].z); bp[3] = f2tf32(br[hh].w);
    }
    __syncthreads();

    for (int it = 0; it < niter; it++) {
        int buf = it & 1;
        bool hasNext = (it + 1) < niter;
        if (hasNext) {
            int k0 = (it + 1) << 4;
#pragma unroll
            for (int hh = 0; hh < 2; hh++) {
                ar[hh] = *reinterpret_cast<const float4*>(
                    A + (size_t)(bm + lr + hh * 64) * lda + k0 + lc);
                int n = bn + lr + hh * 64;
                br[hh] = (n < N)
                    ? *reinterpret_cast<const float4*>(Wt + (size_t)n * K + k0 + lc)
                    : make_float4(0.f, 0.f, 0.f, 0.f);
            }
        }
        // ---- compute on smem[buf] ----
#pragma unroll
        for (int ks = 0; ks < 2; ks++) {
            int k0 = ks * 8;
            uint32_t af[2][4];
#pragma unroll
            for (int mt = 0; mt < 2; mt++) {
                int mr = wm + mt * 16 + gid;
                af[mt][0] = As[buf][mr][k0 + tig];
                af[mt][1] = As[buf][mr + 8][k0 + tig];
                af[mt][2] = As[buf][mr][k0 + tig + 4];
                af[mt][3] = As[buf][mr + 8][k0 + tig + 4];
            }
#pragma unroll
            for (int nt = 0; nt < 8; nt++) {
                int nr = wn + nt * 8 + gid;
                uint32_t b0 = Bs[buf][nr][k0 + tig];
                uint32_t b1 = Bs[buf][nr][k0 + tig + 4];
#pragma unroll
                for (int mt = 0; mt < 2; mt++)
                    mma_tf32(acc[mt][nt], af[mt], b0, b1);
            }
        }
        if (hasNext) {
            int nb = buf ^ 1;
#pragma unroll
            for (int hh = 0; hh < 2; hh++) {
                uint32_t* ap = &As[nb][lr + hh * 64][lc];
                ap[0] = f2tf32(ar[hh].x); ap[1] = f2tf32(ar[hh].y);
                ap[2] = f2tf32(ar[hh].z); ap[3] = f2tf32(ar[hh].w);
                uint32_t* bp = &Bs[nb][lr + hh * 64][lc];
                bp[0] = f2tf32(br[hh].x); bp[1] = f2tf32(br[hh].y);
                bp[2] = f2tf32(br[hh].z); bp[3] = f2tf32(br[hh].w);
            }
        }
        __syncthreads();
    }

    // ---- epilogue ----
#pragma unroll
    for (int nt = 0; nt < 8; nt++) {
        int col = bn + wn + nt * 8 + tig * 2;
        if (col >= N) continue;
        float b0 = bias[col], b1 = bias[col + 1];
#pragma unroll
        for (int mt = 0; mt < 2; mt++) {
            int row0 = bm + wm + mt * 16 + gid;
#pragma unroll
            for (int half = 0; half < 2; half++) {
                int row = row0 + half * 8;
                float v0 = acc[mt][nt][half * 2 + 0] + b0;
                float v1 = acc[mt][nt][half * 2 + 1] + b1;
                if (EPI == 1) {
                    const float2 r = *reinterpret_cast<const float2*>(
                        resid + (size_t)row * ldr + col);
                    v0 += r.x; v1 += r.y;
                }
                if (EPI == 2) {
                    v0 = 0.5f * v0 * (1.f + erff(v0 * 0.70710678118654752f));
                    v1 = 0.5f * v1 * (1.f + erff(v1 * 0.70710678118654752f));
                }
                *reinterpret_cast<float2*>(Cout + (size_t)row * ldc + col) =
                    make_float2(v0, v1);
            }
        }
    }
}

// ---------------- deformable sampling + 4-point attention -------------------
__global__ __launch_bounds__(128) void deform_attn_kernel(
    const float* __restrict__ qkv, const float* __restrict__ off,
    const float* __restrict__ refp, float* __restrict__ out)
{
    int gwarp = (blockIdx.x * blockDim.x + threadIdx.x) >> 5;
    int lane = threadIdx.x & 31;
    int n = gwarp % NQ;
    int bh = gwarp / NQ;
    int h = bh % HEADS;
    int b = bh / HEADS;

    const float* row = qkv + ((size_t)b * NQ + n) * C3;
    float q0 = row[h * HDQ + lane];
    float q1 = row[h * HDQ + 32 + lane];
    const float* op = off + ((size_t)b * NQ + n) * (HEADS * PTS * 2) + h * PTS * 2;
    float rx = refp[((size_t)b * NQ + n) * 2 + 0];
    float ry = refp[((size_t)b * NQ + n) * 2 + 1];

    const float* kbase = qkv + (size_t)b * NQ * C3 + CQ + h * HDQ;

    float sv0[PTS], sv1[PTS], logit[PTS];
#pragma unroll
    for (int p = 0; p < PTS; p++) {
        float x = rx * (float)IMG_W + op[p * 2 + 0] - 0.5f;
        float y = ry * (float)IMG_H + op[p * 2 + 1] - 0.5f;
        float xf = floorf(x), yf = floorf(y);
        float wx = x - xf, wy = y - yf;
        int x0 = (int)xf, y0 = (int)yf;
        float wgt[4];
        wgt[0] = (1.f - wx) * (1.f - wy);
        wgt[1] = wx * (1.f - wy);
        wgt[2] = (1.f - wx) * wy;
        wgt[3] = wx * wy;
        float k0 = 0.f, k1 = 0.f, v0 = 0.f, v1 = 0.f;
#pragma unroll
        for (int c = 0; c < 4; c++) {
            int ix = x0 + (c & 1);
            int iy = y0 + (c >> 1);
            if (ix >= 0 && ix < IMG_W && iy >= 0 && iy < IMG_H) {
                float w = wgt[c];
                const float* kp = kbase + (size_t)(iy * IMG_W + ix) * C3;
                k0 += w * kp[lane];
                k1 += w * kp[32 + lane];
                v0 += w * kp[CQ + lane];
                v1 += w * kp[CQ + 32 + lane];
            }
        }
        sv0[p] = v0;
        sv1[p] = v1;
        float part = q0 * k0 + q1 * k1;
#pragma unroll
        for (int o = 16; o > 0; o >>= 1)
            part += __shfl_xor_sync(0xffffffffu, part, o);
        logit[p] = part * 0.125f;   // HD^-0.5
    }
    float mx = fmaxf(fmaxf(logit[0], logit[1]), fmaxf(logit[2], logit[3]));
    float e[PTS], esum = 0.f;
#pragma unroll
    for (int p = 0; p < PTS; p++) { e[p] = expf(logit[p] - mx); esum += e[p]; }
    float inv = 1.f / esum;
    float o0 = 0.f, o1 = 0.f;
#pragma unroll
    for (int p = 0; p < PTS; p++) {
        float a = e[p] * inv;
        o0 += a * sv0[p];
        o1 += a * sv1[p];
    }
    float* orow = out + ((size_t)b * NQ + n) * CQ + h * HDQ;
    orow[lane] = o0;
    orow[32 + lane] = o1;
}

// ---------------- launch ----------------------------------------------------
extern "C" void kernel_launch(void* const* d_in, const int* in_sizes, int n_in,
                              void* d_out, int out_size)
{
    (void)in_sizes; (void)n_in; (void)out_size;
    const float* x      = (const float*)d_in[0];
    const float* refp   = (const float*)d_in[1];
    const float* n1w    = (const float*)d_in[2];
    const float* n1b    = (const float*)d_in[3];
    const float* qkv_w  = (const float*)d_in[4];
    const float* qkv_b  = (const float*)d_in[5];
    const float* off_w  = (const float*)d_in[6];
    const float* off_b  = (const float*)d_in[7];
    const float* proj_w = (const float*)d_in[8];
    const float* proj_b = (const float*)d_in[9];
    const float* n2w    = (const float*)d_in[10];
    const float* n2b    = (const float*)d_in[11];
    const float* fc1_w  = (const float*)d_in[12];
    const float* fc1_b  = (const float*)d_in[13];
    const float* fc2_w  = (const float*)d_in[14];
    const float* fc2_b  = (const float*)d_in[15];
    float* out = (float*)d_out;

    float *h_p, *qkv_p, *off_p, *attn_p, *x1_p, *m_p;
    cudaGetSymbolAddress((void**)&h_p,    g_h);
    cudaGetSymbolAddress((void**)&qkv_p,  g_qkv);
    cudaGetSymbolAddress((void**)&off_p,  g_off);
    cudaGetSymbolAddress((void**)&attn_p, g_attn);
    cudaGetSymbolAddress((void**)&x1_p,   g_x1);
    cudaGetSymbolAddress((void**)&m_p,    g_m);

    // 1. h = LN1(x)
    ln_kernel<<<M_ROWS, 256>>>(x, n1w, n1b, h_p);
    // 2. qkv = h @ qkv_w.T + qkv_b
    gemm_tf32<0><<<dim3(C3 / 128, M_ROWS / 128), 256>>>(
        h_p, CQ, qkv_w, qkv_b, nullptr, 0, qkv_p, C3, M_ROWS, C3, CQ);
    // 3. offsets = q @ off_w.T + off_b   (q = qkv[:, :768] via lda; N=96 guarded)
    gemm_tf32<0><<<dim3(1, M_ROWS / 128), 256>>>(
        qkv_p, C3, off_w, off_b, nullptr, 0, off_p, HEADS * PTS * 2,
        M_ROWS, HEADS * PTS * 2, CQ);
    // 4. deformable sampling + attention
    deform_attn_kernel<<<(M_ROWS * HEADS) / 4, 128>>>(qkv_p, off_p, refp, attn_p);
    // 5. x1 = x + attn @ proj_w.T + proj_b
    gemm_tf32<1><<<dim3(CQ / 128, M_ROWS / 128), 256>>>(
        attn_p, CQ, proj_w, proj_b, x, CQ, x1_p, CQ, M_ROWS, CQ, CQ);
    // 6. h2 = LN2(x1)
    ln_kernel<<<M_ROWS, 256>>>(x1_p, n2w, n2b, h_p);
    // 7. m = gelu(h2 @ fc1_w.T + fc1_b)
    gemm_tf32<2><<<dim3(HID / 128, M_ROWS / 128), 256>>>(
        h_p, CQ, fc1_w, fc1_b, nullptr, 0, m_p, HID, M_ROWS, HID, CQ);
    // 8. out = x1 + m @ fc2_w.T + fc2_b
    gemm_tf32<1><<<dim3(CQ / 128, M_ROWS / 128), 256>>>(
        m_p, HID, fc2_w, fc2_b, x1_p, CQ, out, CQ, M_ROWS, CQ, HID);
}

// round 12
// speedup vs baseline: 2.7377x; 1.1468x over previous
#include <cuda_runtime.h>
#include <math.h>
#include <stdint.h>

#define BQ 4
#define NQ 4096
#define CQ 768
#define HEADS 12
#define PTS 4
#define HDQ 64
#define HID 3072
#define IMG_H 64
#define IMG_W 64
#define C3 (3*CQ)
#define M_ROWS (BQ*NQ)   /* 16384 */

// ---------------- scratch (static device arrays; no allocation) -------------
__device__ float g_h[(size_t)M_ROWS * CQ];        // LN1 out, reused for LN2 out
__device__ float g_qkv[(size_t)M_ROWS * C3];
__device__ float g_off[(size_t)M_ROWS * HEADS * PTS * 2];
__device__ float g_attn[(size_t)M_ROWS * CQ];
__device__ float g_x1[(size_t)M_ROWS * CQ];
__device__ float g_m[(size_t)M_ROWS * HID];

// ---------------- LayerNorm: one block per row, C = 768 ---------------------
__global__ __launch_bounds__(256) void ln_kernel(
    const float* __restrict__ x, const float* __restrict__ gw,
    const float* __restrict__ gb, float* __restrict__ out)
{
    __shared__ float s_sum[8], s_sq[8];
    int row = blockIdx.x;
    const float* xr = x + (size_t)row * CQ;
    float v[3];
    float s = 0.f, sq = 0.f;
#pragma unroll
    for (int i = 0; i < 3; i++) {
        v[i] = xr[threadIdx.x + i * 256];
        s += v[i];
        sq += v[i] * v[i];
    }
#pragma unroll
    for (int o = 16; o > 0; o >>= 1) {
        s  += __shfl_xor_sync(0xffffffffu, s,  o);
        sq += __shfl_xor_sync(0xffffffffu, sq, o);
    }
    int w = threadIdx.x >> 5, l = threadIdx.x & 31;
    if (l == 0) { s_sum[w] = s; s_sq[w] = sq; }
    __syncthreads();
    if (w == 0) {
        s  = (l < 8) ? s_sum[l] : 0.f;
        sq = (l < 8) ? s_sq[l]  : 0.f;
#pragma unroll
        for (int o = 4; o > 0; o >>= 1) {
            s  += __shfl_xor_sync(0xffffffffu, s,  o);
            sq += __shfl_xor_sync(0xffffffffu, sq, o);
        }
        if (l == 0) { s_sum[0] = s; s_sq[0] = sq; }
    }
    __syncthreads();
    float mean = s_sum[0] * (1.f / CQ);
    float var  = s_sq[0] * (1.f / CQ) - mean * mean;
    float rstd = rsqrtf(var + 1e-5f);
#pragma unroll
    for (int i = 0; i < 3; i++) {
        int c = threadIdx.x + i * 256;
        out[(size_t)row * CQ + c] = (v[i] - mean) * rstd * gw[c] + gb[c];
    }
}

// ---------------- TF32 tensor-core GEMM with cp.async pipeline --------------
// C[m,n] = sum_k A[m,k] * W[n,k] + bias[n]   (EPI 0: bias, 1: +resid, 2: GELU)
// Raw fp32 bits fed to mma.tf32 (HW truncation, CUTLASS-standard).
// 2-stage cp.async.cg global->smem, no register staging, no CVT/STS.
__device__ __forceinline__ void cp_a16(uint32_t dst, const void* src, bool pred) {
    int sz = pred ? 16 : 0;
    asm volatile("cp.async.cg.shared.global [%0], [%1], 16, %2;\n"
                 :: "r"(dst), "l"(src), "r"(sz));
}

__device__ __forceinline__ void mma_tf32(
    float c[4], const uint32_t a[4], uint32_t b0, uint32_t b1)
{
    asm volatile(
        "mma.sync.aligned.m16n8k8.row.col.f32.tf32.tf32.f32 "
        "{%0,%1,%2,%3}, {%4,%5,%6,%7}, {%8,%9}, {%0,%1,%2,%3};"
        : "+f"(c[0]), "+f"(c[1]), "+f"(c[2]), "+f"(c[3])
        : "r"(a[0]), "r"(a[1]), "r"(a[2]), "r"(a[3]), "r"(b0), "r"(b1));
}

template <int EPI>
__global__ __launch_bounds__(256) void gemm_tf32(
    const float* __restrict__ A, int lda,
    const float* __restrict__ Wt,
    const float* __restrict__ bias,
    const float* __restrict__ resid, int ldr,
    float* __restrict__ Cout, int ldc,
    int M, int N, int K)
{
    __shared__ uint32_t As[2][128][20];
    __shared__ uint32_t Bs[2][128][20];

    int tid  = threadIdx.x;
    int bm   = blockIdx.y * 128;
    int bn   = blockIdx.x * 128;
    int w    = tid >> 5;
    int lane = tid & 31;
    int gid  = lane >> 2;
    int tig  = lane & 3;
    int wm   = (w & 3) * 32;
    int wn   = (w >> 2) * 64;

    int lr   = tid >> 2;      // 0..63 load row
    int lc   = (tid & 3) * 4; // float4 col offset

    float acc[2][8][4];
#pragma unroll
    for (int mt = 0; mt < 2; mt++)
#pragma unroll
        for (int nt = 0; nt < 8; nt++)
#pragma unroll
            for (int i = 0; i < 4; i++) acc[mt][nt][i] = 0.f;

    int niter = K >> 4;

    // precompute smem dst addresses (stage 0/1, hh 0/1)
    uint32_t a_dst[2][2], b_dst[2][2];
#pragma unroll
    for (int s = 0; s < 2; s++)
#pragma unroll
        for (int hh = 0; hh < 2; hh++) {
            a_dst[s][hh] = (uint32_t)__cvta_generic_to_shared(&As[s][lr + hh * 64][lc]);
            b_dst[s][hh] = (uint32_t)__cvta_generic_to_shared(&Bs[s][lr + hh * 64][lc]);
        }

    // ---- issue stage 0 ----
#pragma unroll
    for (int hh = 0; hh < 2; hh++) {
        cp_a16(a_dst[0][hh], A + (size_t)(bm + lr + hh * 64) * lda + lc, true);
        int n = bn + lr + hh * 64;
        const float* bsrc = (n < N) ? (Wt + (size_t)n * K + lc) : Wt;
        cp_a16(b_dst[0][hh], bsrc, n < N);
    }
    asm volatile("cp.async.commit_group;\n" ::: "memory");

    for (int it = 0; it < niter; it++) {
        int cur = it & 1;
        if (it + 1 < niter) {
            int k0 = (it + 1) << 4;
            int nxt = cur ^ 1;
#pragma unroll
            for (int hh = 0; hh < 2; hh++) {
                cp_a16(a_dst[nxt][hh], A + (size_t)(bm + lr + hh * 64) * lda + k0 + lc, true);
                int n = bn + lr + hh * 64;
                const float* bsrc = (n < N) ? (Wt + (size_t)n * K + k0 + lc) : Wt;
                cp_a16(b_dst[nxt][hh], bsrc, n < N);
            }
        }
        asm volatile("cp.async.commit_group;\n" ::: "memory");
        asm volatile("cp.async.wait_group 1;\n" ::: "memory");
        __syncthreads();

        // ---- compute on smem[cur] ----
#pragma unroll
        for (int ks = 0; ks < 2; ks++) {
            int k0 = ks * 8;
            uint32_t af[2][4];
#pragma unroll
            for (int mt = 0; mt < 2; mt++) {
                int mr = wm + mt * 16 + gid;
                af[mt][0] = As[cur][mr][k0 + tig];
                af[mt][1] = As[cur][mr + 8][k0 + tig];
                af[mt][2] = As[cur][mr][k0 + tig + 4];
                af[mt][3] = As[cur][mr + 8][k0 + tig + 4];
            }
#pragma unroll
            for (int nt = 0; nt < 8; nt++) {
                int nr = wn + nt * 8 + gid;
                uint32_t b0 = Bs[cur][nr][k0 + tig];
                uint32_t b1 = Bs[cur][nr][k0 + tig + 4];
#pragma unroll
                for (int mt = 0; mt < 2; mt++)
                    mma_tf32(acc[mt][nt], af[mt], b0, b1);
            }
        }
        __syncthreads();
    }

    // ---- epilogue ----
#pragma unroll
    for (int nt = 0; nt < 8; nt++) {
        int col = bn + wn + nt * 8 + tig * 2;
        if (col >= N) continue;
        float b0 = bias[col], b1 = bias[col + 1];
#pragma unroll
        for (int mt = 0; mt < 2; mt++) {
            int row0 = bm + wm + mt * 16 + gid;
#pragma unroll
            for (int half = 0; half < 2; half++) {
                int row = row0 + half * 8;
                float v0 = acc[mt][nt][half * 2 + 0] + b0;
                float v1 = acc[mt][nt][half * 2 + 1] + b1;
                if (EPI == 1) {
                    const float2 r = *reinterpret_cast<const float2*>(
                        resid + (size_t)row * ldr + col);
                    v0 += r.x; v1 += r.y;
                }
                if (EPI == 2) {
                    v0 = 0.5f * v0 * (1.f + erff(v0 * 0.70710678118654752f));
                    v1 = 0.5f * v1 * (1.f + erff(v1 * 0.70710678118654752f));
                }
                *reinterpret_cast<float2*>(Cout + (size_t)row * ldc + col) =
                    make_float2(v0, v1);
            }
        }
    }
}

// ---------------- deformable sampling + 4-point attention -------------------
__global__ __launch_bounds__(128) void deform_attn_kernel(
    const float* __restrict__ qkv, const float* __restrict__ off,
    const float* __restrict__ refp, float* __restrict__ out)
{
    int gwarp = (blockIdx.x * blockDim.x + threadIdx.x) >> 5;
    int lane = threadIdx.x & 31;
    int n = gwarp % NQ;
    int bh = gwarp / NQ;
    int h = bh % HEADS;
    int b = bh / HEADS;

    const float* row = qkv + ((size_t)b * NQ + n) * C3;
    float q0 = row[h * HDQ + lane];
    float q1 = row[h * HDQ + 32 + lane];
    const float* op = off + ((size_t)b * NQ + n) * (HEADS * PTS * 2) + h * PTS * 2;
    float rx = refp[((size_t)b * NQ + n) * 2 + 0];
    float ry = refp[((size_t)b * NQ + n) * 2 + 1];

    const float* kbase = qkv + (size_t)b * NQ * C3 + CQ + h * HDQ;

    float sv0[PTS], sv1[PTS], logit[PTS];
#pragma unroll
    for (int p = 0; p < PTS; p++) {
        float x = rx * (float)IMG_W + op[p * 2 + 0] - 0.5f;
        float y = ry * (float)IMG_H + op[p * 2 + 1] - 0.5f;
        float xf = floorf(x), yf = floorf(y);
        float wx = x - xf, wy = y - yf;
        int x0 = (int)xf, y0 = (int)yf;
        float wgt[4];
        wgt[0] = (1.f - wx) * (1.f - wy);
        wgt[1] = wx * (1.f - wy);
        wgt[2] = (1.f - wx) * wy;
        wgt[3] = wx * wy;
        float k0 = 0.f, k1 = 0.f, v0 = 0.f, v1 = 0.f;
#pragma unroll
        for (int c = 0; c < 4; c++) {
            int ix = x0 + (c & 1);
            int iy = y0 + (c >> 1);
            if (ix >= 0 && ix < IMG_W && iy >= 0 && iy < IMG_H) {
                float w = wgt[c];
                const float* kp = kbase + (size_t)(iy * IMG_W + ix) * C3;
                k0 += w * kp[lane];
                k1 += w * kp[32 + lane];
                v0 += w * kp[CQ + lane];
                v1 += w * kp[CQ + 32 + lane];
            }
        }
        sv0[p] = v0;
        sv1[p] = v1;
        float part = q0 * k0 + q1 * k1;
#pragma unroll
        for (int o = 16; o > 0; o >>= 1)
            part += __shfl_xor_sync(0xffffffffu, part, o);
        logit[p] = part * 0.125f;   // HD^-0.5
    }
    float mx = fmaxf(fmaxf(logit[0], logit[1]), fmaxf(logit[2], logit[3]));
    float e[PTS], esum = 0.f;
#pragma unroll
    for (int p = 0; p < PTS; p++) { e[p] = expf(logit[p] - mx); esum += e[p]; }
    float inv = 1.f / esum;
    float o0 = 0.f, o1 = 0.f;
#pragma unroll
    for (int p = 0; p < PTS; p++) {
        float a = e[p] * inv;
        o0 += a * sv0[p];
        o1 += a * sv1[p];
    }
    float* orow = out + ((size_t)b * NQ + n) * CQ + h * HDQ;
    orow[lane] = o0;
    orow[32 + lane] = o1;
}

// ---------------- launch ----------------------------------------------------
extern "C" void kernel_launch(void* const* d_in, const int* in_sizes, int n_in,
                              void* d_out, int out_size)
{
    (void)in_sizes; (void)n_in; (void)out_size;
    const float* x      = (const float*)d_in[0];
    const float* refp   = (const float*)d_in[1];
    const float* n1w    = (const float*)d_in[2];
    const float* n1b    = (const float*)d_in[3];
    const float* qkv_w  = (const float*)d_in[4];
    const float* qkv_b  = (const float*)d_in[5];
    const float* off_w  = (const float*)d_in[6];
    const float* off_b  = (const float*)d_in[7];
    const float* proj_w = (const float*)d_in[8];
    const float* proj_b = (const float*)d_in[9];
    const float* n2w    = (const float*)d_in[10];
    const float* n2b    = (const float*)d_in[11];
    const float* fc1_w  = (const float*)d_in[12];
    const float* fc1_b  = (const float*)d_in[13];
    const float* fc2_w  = (const float*)d_in[14];
    const float* fc2_b  = (const float*)d_in[15];
    float* out = (float*)d_out;

    float *h_p, *qkv_p, *off_p, *attn_p, *x1_p, *m_p;
    cudaGetSymbolAddress((void**)&h_p,    g_h);
    cudaGetSymbolAddress((void**)&qkv_p,  g_qkv);
    cudaGetSymbolAddress((void**)&off_p,  g_off);
    cudaGetSymbolAddress((void**)&attn_p, g_attn);
    cudaGetSymbolAddress((void**)&x1_p,   g_x1);
    cudaGetSymbolAddress((void**)&m_p,    g_m);

    // 1. h = LN1(x)
    ln_kernel<<<M_ROWS, 256>>>(x, n1w, n1b, h_p);
    // 2. qkv = h @ qkv_w.T + qkv_b
    gemm_tf32<0><<<dim3(C3 / 128, M_ROWS / 128), 256>>>(
        h_p, CQ, qkv_w, qkv_b, nullptr, 0, qkv_p, C3, M_ROWS, C3, CQ);
    // 3. offsets = q @ off_w.T + off_b   (q = qkv[:, :768] via lda; N=96 guarded)
    gemm_tf32<0><<<dim3(1, M_ROWS / 128), 256>>>(
        qkv_p, C3, off_w, off_b, nullptr, 0, off_p, HEADS * PTS * 2,
        M_ROWS, HEADS * PTS * 2, CQ);
    // 4. deformable sampling + attention
    deform_attn_kernel<<<(M_ROWS * HEADS) / 4, 128>>>(qkv_p, off_p, refp, attn_p);
    // 5. x1 = x + attn @ proj_w.T + proj_b
    gemm_tf32<1><<<dim3(CQ / 128, M_ROWS / 128), 256>>>(
        attn_p, CQ, proj_w, proj_b, x, CQ, x1_p, CQ, M_ROWS, CQ, CQ);
    // 6. h2 = LN2(x1)
    ln_kernel<<<M_ROWS, 256>>>(x1_p, n2w, n2b, h_p);
    // 7. m = gelu(h2 @ fc1_w.T + fc1_b)
    gemm_tf32<2><<<dim3(HID / 128, M_ROWS / 128), 256>>>(
        h_p, CQ, fc1_w, fc1_b, nullptr, 0, m_p, HID, M_ROWS, HID, CQ);
    // 8. out = x1 + m @ fc2_w.T + fc2_b
    gemm_tf32<1><<<dim3(CQ / 128, M_ROWS / 128), 256>>>(
        m_p, HID, fc2_w, fc2_b, x1_p, CQ, out, CQ, M_ROWS, CQ, HID);
}

// round 17
// speedup vs baseline: 2.9181x; 1.0659x over previous
#include <cuda_runtime.h>
#include <math.h>
#include <stdint.h>

#define BQ 4
#define NQ 4096
#define CQ 768
#define HEADS 12
#define PTS 4
#define HDQ 64
#define HID 3072
#define IMG_H 64
#define IMG_W 64
#define C3 (3*CQ)
#define M_ROWS (BQ*NQ)   /* 16384 */

// ---------------- scratch (static device arrays; no allocation) -------------
__device__ float g_h[(size_t)M_ROWS * CQ];        // LN1 out, reused for LN2 out
__device__ float g_qkv[(size_t)M_ROWS * C3];
__device__ float g_off[(size_t)M_ROWS * HEADS * PTS * 2];
__device__ float g_attn[(size_t)M_ROWS * CQ];
__device__ float g_x1[(size_t)M_ROWS * CQ];
__device__ float g_m[(size_t)M_ROWS * HID];

// ---------------- LayerNorm: one block per row, C = 768 ---------------------
__global__ __launch_bounds__(256) void ln_kernel(
    const float* __restrict__ x, const float* __restrict__ gw,
    const float* __restrict__ gb, float* __restrict__ out)
{
    __shared__ float s_sum[8], s_sq[8];
    int row = blockIdx.x;
    const float* xr = x + (size_t)row * CQ;
    float v[3];
    float s = 0.f, sq = 0.f;
#pragma unroll
    for (int i = 0; i < 3; i++) {
        v[i] = xr[threadIdx.x + i * 256];
        s += v[i];
        sq += v[i] * v[i];
    }
#pragma unroll
    for (int o = 16; o > 0; o >>= 1) {
        s  += __shfl_xor_sync(0xffffffffu, s,  o);
        sq += __shfl_xor_sync(0xffffffffu, sq, o);
    }
    int w = threadIdx.x >> 5, l = threadIdx.x & 31;
    if (l == 0) { s_sum[w] = s; s_sq[w] = sq; }
    __syncthreads();
    if (w == 0) {
        s  = (l < 8) ? s_sum[l] : 0.f;
        sq = (l < 8) ? s_sq[l]  : 0.f;
#pragma unroll
        for (int o = 4; o > 0; o >>= 1) {
            s  += __shfl_xor_sync(0xffffffffu, s,  o);
            sq += __shfl_xor_sync(0xffffffffu, sq, o);
        }
        if (l == 0) { s_sum[0] = s; s_sq[0] = sq; }
    }
    __syncthreads();
    float mean = s_sum[0] * (1.f / CQ);
    float var  = s_sq[0] * (1.f / CQ) - mean * mean;
    float rstd = rsqrtf(var + 1e-5f);
#pragma unroll
    for (int i = 0; i < 3; i++) {
        int c = threadIdx.x + i * 256;
        out[(size_t)row * CQ + c] = (v[i] - mean) * rstd * gw[c] + gb[c];
    }
}

// ---------------- TF32 tensor-core GEMM: cp.async + ldmatrix ----------------
// C[m,n] = sum_k A[m,k] * W[n,k] + bias[n]   (EPI 0: bias, 1: +resid, 2: GELU)
// Raw fp32 bits to mma.tf32 (HW truncation). Fragments fed via ldmatrix.x4:
// m8n8.b16 distribution (thread t <- 4B word t%4 of row t/4) == tf32 fragment
// layout when each 16B "row" is 4 tf32 of one k-half.
__device__ __forceinline__ void cp_a16(uint32_t dst, const void* src, bool pred) {
    int sz = pred ? 16 : 0;
    asm volatile("cp.async.cg.shared.global [%0], [%1], 16, %2;\n"
                 :: "r"(dst), "l"(src), "r"(sz));
}

__device__ __forceinline__ void ldsm_x4(
    uint32_t& r0, uint32_t& r1, uint32_t& r2, uint32_t& r3, uint32_t addr)
{
    asm volatile("ldmatrix.sync.aligned.m8n8.x4.shared.b16 {%0,%1,%2,%3}, [%4];"
                 : "=r"(r0), "=r"(r1), "=r"(r2), "=r"(r3) : "r"(addr));
}

__device__ __forceinline__ void mma_tf32(
    float c[4], const uint32_t a[4], uint32_t b0, uint32_t b1)
{
    asm volatile(
        "mma.sync.aligned.m16n8k8.row.col.f32.tf32.tf32.f32 "
        "{%0,%1,%2,%3}, {%4,%5,%6,%7}, {%8,%9}, {%0,%1,%2,%3};"
        : "+f"(c[0]), "+f"(c[1]), "+f"(c[2]), "+f"(c[3])
        : "r"(a[0]), "r"(a[1]), "r"(a[2]), "r"(a[3]), "r"(b0), "r"(b1));
}

template <int EPI>
__global__ __launch_bounds__(256) void gemm_tf32(
    const float* __restrict__ A, int lda,
    const float* __restrict__ Wt,
    const float* __restrict__ bias,
    const float* __restrict__ resid, int ldr,
    float* __restrict__ Cout, int ldc,
    int M, int N, int K)
{
    __shared__ uint32_t As[2][128][20];
    __shared__ uint32_t Bs[2][128][20];

    int tid  = threadIdx.x;
    int bm   = blockIdx.y * 128;
    int bn   = blockIdx.x * 128;
    int w    = tid >> 5;
    int lane = tid & 31;
    int gid  = lane >> 2;
    int tig  = lane & 3;
    int wm   = (w & 3) * 32;
    int wn   = (w >> 2) * 64;

    int lr   = tid >> 2;      // 0..63 load row
    int lc   = (tid & 3) * 4; // float4 col offset

    // ldmatrix per-lane sub-tile offsets (s = lane>>3 selects submatrix)
    int l7 = lane & 7;
    int s8 = lane >> 3;                       // 0..3
    int a_row = l7 + (s8 & 1) * 8;            // subs {rows, rows+8} x {k, k+4}
    int a_wrd = (s8 >> 1) * 4;
    int b_row = l7 + (s8 >> 1) * 8;           // subs {k, k+4} x {rows, rows+8}
    int b_wrd = (s8 & 1) * 4;

    uint32_t aFrag[2], bFrag[2];
#pragma unroll
    for (int st = 0; st < 2; st++) {
        aFrag[st] = (uint32_t)__cvta_generic_to_shared(&As[st][wm + a_row][a_wrd]);
        bFrag[st] = (uint32_t)__cvta_generic_to_shared(&Bs[st][wn + b_row][b_wrd]);
    }

    float acc[2][8][4];
#pragma unroll
    for (int mt = 0; mt < 2; mt++)
#pragma unroll
        for (int nt = 0; nt < 8; nt++)
#pragma unroll
            for (int i = 0; i < 4; i++) acc[mt][nt][i] = 0.f;

    int niter = K >> 4;

    uint32_t a_dst[2][2], b_dst[2][2];
#pragma unroll
    for (int st = 0; st < 2; st++)
#pragma unroll
        for (int hh = 0; hh < 2; hh++) {
            a_dst[st][hh] = (uint32_t)__cvta_generic_to_shared(&As[st][lr + hh * 64][lc]);
            b_dst[st][hh] = (uint32_t)__cvta_generic_to_shared(&Bs[st][lr + hh * 64][lc]);
        }

    // ---- issue stage 0 ----
#pragma unroll
    for (int hh = 0; hh < 2; hh++) {
        cp_a16(a_dst[0][hh], A + (size_t)(bm + lr + hh * 64) * lda + lc, true);
        int n = bn + lr + hh * 64;
        const float* bsrc = (n < N) ? (Wt + (size_t)n * K + lc) : Wt;
        cp_a16(b_dst[0][hh], bsrc, n < N);
    }
    asm volatile("cp.async.commit_group;\n" ::: "memory");

    for (int it = 0; it < niter; it++) {
        int cur = it & 1;
        if (it + 1 < niter) {
            int k0 = (it + 1) << 4;
            int nxt = cur ^ 1;
#pragma unroll
            for (int hh = 0; hh < 2; hh++) {
                cp_a16(a_dst[nxt][hh], A + (size_t)(bm + lr + hh * 64) * lda + k0 + lc, true);
                int n = bn + lr + hh * 64;
                const float* bsrc = (n < N) ? (Wt + (size_t)n * K + k0 + lc) : Wt;
                cp_a16(b_dst[nxt][hh], bsrc, n < N);
            }
        }
        asm volatile("cp.async.commit_group;\n" ::: "memory");
        asm volatile("cp.async.wait_group 1;\n" ::: "memory");
        __syncthreads();

        // ---- compute on smem[cur] via ldmatrix ----
#pragma unroll
        for (int ks = 0; ks < 2; ks++) {
            uint32_t af[2][4];
#pragma unroll
            for (int mt = 0; mt < 2; mt++)
                ldsm_x4(af[mt][0], af[mt][1], af[mt][2], af[mt][3],
                        aFrag[cur] + (uint32_t)((mt * 16 * 20 + ks * 8) * 4));
#pragma unroll
            for (int np = 0; np < 4; np++) {
                uint32_t b00, b01, b10, b11;   // (nt=2np: b0,b1), (nt=2np+1: b0,b1)
                ldsm_x4(b00, b01, b10, b11,
                        bFrag[cur] + (uint32_t)((np * 16 * 20 + ks * 8) * 4));
#pragma unroll
                for (int mt = 0; mt < 2; mt++) {
                    mma_tf32(acc[mt][np * 2 + 0], af[mt], b00, b01);
                    mma_tf32(acc[mt][np * 2 + 1], af[mt], b10, b11);
                }
            }
        }
        __syncthreads();
    }

    // ---- epilogue ----
#pragma unroll
    for (int nt = 0; nt < 8; nt++) {
        int col = bn + wn + nt * 8 + tig * 2;
        if (col >= N) continue;
        float b0 = bias[col], b1 = bias[col + 1];
#pragma unroll
        for (int mt = 0; mt < 2; mt++) {
            int row0 = bm + wm + mt * 16 + gid;
#pragma unroll
            for (int half = 0; half < 2; half++) {
                int row = row0 + half * 8;
                float v0 = acc[mt][nt][half * 2 + 0] + b0;
                float v1 = acc[mt][nt][half * 2 + 1] + b1;
                if (EPI == 1) {
                    const float2 r = *reinterpret_cast<const float2*>(
                        resid + (size_t)row * ldr + col);
                    v0 += r.x; v1 += r.y;
                }
                if (EPI == 2) {
                    v0 = 0.5f * v0 * (1.f + erff(v0 * 0.70710678118654752f));
                    v1 = 0.5f * v1 * (1.f + erff(v1 * 0.70710678118654752f));
                }
                *reinterpret_cast<float2*>(Cout + (size_t)row * ldc + col) =
                    make_float2(v0, v1);
            }
        }
    }
}

// ---------------- deformable sampling + 4-point attention -------------------
__global__ __launch_bounds__(128) void deform_attn_kernel(
    const float* __restrict__ qkv, const float* __restrict__ off,
    const float* __restrict__ refp, float* __restrict__ out)
{
    int gwarp = (blockIdx.x * blockDim.x + threadIdx.x) >> 5;
    int lane = threadIdx.x & 31;
    int n = gwarp % NQ;
    int bh = gwarp / NQ;
    int h = bh % HEADS;
    int b = bh / HEADS;

    const float* row = qkv + ((size_t)b * NQ + n) * C3;
    float q0 = row[h * HDQ + lane];
    float q1 = row[h * HDQ + 32 + lane];
    const float* op = off + ((size_t)b * NQ + n) * (HEADS * PTS * 2) + h * PTS * 2;
    float rx = refp[((size_t)b * NQ + n) * 2 + 0];
    float ry = refp[((size_t)b * NQ + n) * 2 + 1];

    const float* kbase = qkv + (size_t)b * NQ * C3 + CQ + h * HDQ;

    float sv0[PTS], sv1[PTS], logit[PTS];
#pragma unroll
    for (int p = 0; p < PTS; p++) {
        float x = rx * (float)IMG_W + op[p * 2 + 0] - 0.5f;
        float y = ry * (float)IMG_H + op[p * 2 + 1] - 0.5f;
        float xf = floorf(x), yf = floorf(y);
        float wx = x - xf, wy = y - yf;
        int x0 = (int)xf, y0 = (int)yf;
        float wgt[4];
        wgt[0] = (1.f - wx) * (1.f - wy);
        wgt[1] = wx * (1.f - wy);
        wgt[2] = (1.f - wx) * wy;
        wgt[3] = wx * wy;
        float k0 = 0.f, k1 = 0.f, v0 = 0.f, v1 = 0.f;
#pragma unroll
        for (int c = 0; c < 4; c++) {
            int ix = x0 + (c & 1);
            int iy = y0 + (c >> 1);
            if (ix >= 0 && ix < IMG_W && iy >= 0 && iy < IMG_H) {
                float w = wgt[c];
                const float* kp = kbase + (size_t)(iy * IMG_W + ix) * C3;
                k0 += w * kp[lane];
                k1 += w * kp[32 + lane];
                v0 += w * kp[CQ + lane];
                v1 += w * kp[CQ + 32 + lane];
            }
        }
        sv0[p] = v0;
        sv1[p] = v1;
        float part = q0 * k0 + q1 * k1;
#pragma unroll
        for (int o = 16; o > 0; o >>= 1)
            part += __shfl_xor_sync(0xffffffffu, part, o);
        logit[p] = part * 0.125f;   // HD^-0.5
    }
    float mx = fmaxf(fmaxf(logit[0], logit[1]), fmaxf(logit[2], logit[3]));
    float e[PTS], esum = 0.f;
#pragma unroll
    for (int p = 0; p < PTS; p++) { e[p] = expf(logit[p] - mx); esum += e[p]; }
    float inv = 1.f / esum;
    float o0 = 0.f, o1 = 0.f;
#pragma unroll
    for (int p = 0; p < PTS; p++) {
        float a = e[p] * inv;
        o0 += a * sv0[p];
        o1 += a * sv1[p];
    }
    float* orow = out + ((size_t)b * NQ + n) * CQ + h * HDQ;
    orow[lane] = o0;
    orow[32 + lane] = o1;
}

// ---------------- launch ----------------------------------------------------
extern "C" void kernel_launch(void* const* d_in, const int* in_sizes, int n_in,
                              void* d_out, int out_size)
{
    (void)in_sizes; (void)n_in; (void)out_size;
    const float* x      = (const float*)d_in[0];
    const float* refp   = (const float*)d_in[1];
    const float* n1w    = (const float*)d_in[2];
    const float* n1b    = (const float*)d_in[3];
    const float* qkv_w  = (const float*)d_in[4];
    const float* qkv_b  = (const float*)d_in[5];
    const float* off_w  = (const float*)d_in[6];
    const float* off_b  = (const float*)d_in[7];
    const float* proj_w = (const float*)d_in[8];
    const float* proj_b = (const float*)d_in[9];
    const float* n2w    = (const float*)d_in[10];
    const float* n2b    = (const float*)d_in[11];
    const float* fc1_w  = (const float*)d_in[12];
    const float* fc1_b  = (const float*)d_in[13];
    const float* fc2_w  = (const float*)d_in[14];
    const float* fc2_b  = (const float*)d_in[15];
    float* out = (float*)d_out;

    float *h_p, *qkv_p, *off_p, *attn_p, *x1_p, *m_p;
    cudaGetSymbolAddress((void**)&h_p,    g_h);
    cudaGetSymbolAddress((void**)&qkv_p,  g_qkv);
    cudaGetSymbolAddress((void**)&off_p,  g_off);
    cudaGetSymbolAddress((void**)&attn_p, g_attn);
    cudaGetSymbolAddress((void**)&x1_p,   g_x1);
    cudaGetSymbolAddress((void**)&m_p,    g_m);

    // 1. h = LN1(x)
    ln_kernel<<<M_ROWS, 256>>>(x, n1w, n1b, h_p);
    // 2. qkv = h @ qkv_w.T + qkv_b
    gemm_tf32<0><<<dim3(C3 / 128, M_ROWS / 128), 256>>>(
        h_p, CQ, qkv_w, qkv_b, nullptr, 0, qkv_p, C3, M_ROWS, C3, CQ);
    // 3. offsets = q @ off_w.T + off_b   (q = qkv[:, :768] via lda; N=96 guarded)
    gemm_tf32<0><<<dim3(1, M_ROWS / 128), 256>>>(
        qkv_p, C3, off_w, off_b, nullptr, 0, off_p, HEADS * PTS * 2,
        M_ROWS, HEADS * PTS * 2, CQ);
    // 4. deformable sampling + attention
    deform_attn_kernel<<<(M_ROWS * HEADS) / 4, 128>>>(qkv_p, off_p, refp, attn_p);
    // 5. x1 = x + attn @ proj_w.T + proj_b
    gemm_tf32<1><<<dim3(CQ / 128, M_ROWS / 128), 256>>>(
        attn_p, CQ, proj_w, proj_b, x, CQ, x1_p, CQ, M_ROWS, CQ, CQ);
    // 6. h2 = LN2(x1)
    ln_kernel<<<M_ROWS, 256>>>(x1_p, n2w, n2b, h_p);
    // 7. m = gelu(h2 @ fc1_w.T + fc1_b)
    gemm_tf32<2><<<dim3(HID / 128, M_ROWS / 128), 256>>>(
        h_p, CQ, fc1_w, fc1_b, nullptr, 0, m_p, HID, M_ROWS, HID, CQ);
    // 8. out = x1 + m @ fc2_w.T + fc2_b
    gemm_tf32<1><<<dim3(CQ / 128, M_ROWS / 128), 256>>>(
        m_p, HID, fc2_w, fc2_b, x1_p, CQ, out, CQ, M_ROWS, CQ, HID);
}